// round 17
// baseline (speedup 1.0000x reference)
#include <cuda_runtime.h>
#include <cuda_bf16.h>
#include <math.h>

#define EPSV 1e-5f
constexpr int B_ = 4, C_ = 64, N_ = 4096, OUT_ = 128, K_ = 20;
constexpr int HB_ = 16;   // C/4

typedef unsigned long long ull;

// ---------------- scratch (device globals; no allocation allowed) ----------
__device__ __align__(16) __nv_bfloat16 g_pbf[B_ * N_ * 128];  // [B][N][hi64|lo64]
__device__ float g_sq [B_ * N_];                  // squared norms (exact fp32)
__device__ float g_hb [B_ * N_ * HB_];            // bottleneck features [B][N][16]
__device__ int   g_idx[B_ * N_ * K_];             // knn indices
__device__ __align__(16) float g_Wres[OUT_ * C_];
__device__ float g_bres[OUT_];
__device__ __align__(16) float g_Wbot[HB_ * C_];
__device__ float g_bbot[HB_];
__device__ __align__(16) float g_Wg1[32 * 32];
__device__ float g_bg1[32];
__device__ __align__(16) float g_Wg2[32 * 32];
__device__ float g_bg2[32];
__device__ __align__(16) float g_Wdec[OUT_ * 96];
__device__ float g_bdec[OUT_];

struct Params { const float* p[26]; };

// ---------------- mma helpers ----------------------------------------------
__device__ __forceinline__ void ldsm4(unsigned& r0, unsigned& r1, unsigned& r2, unsigned& r3,
                                      unsigned addr) {
    asm volatile("ldmatrix.sync.aligned.m8n8.x4.shared.b16 {%0,%1,%2,%3}, [%4];"
                 : "=r"(r0), "=r"(r1), "=r"(r2), "=r"(r3) : "r"(addr));
}
__device__ __forceinline__ void mma16816(float* c, const unsigned* a, unsigned b0, unsigned b1) {
    asm volatile("mma.sync.aligned.m16n8k16.row.col.f32.bf16.bf16.f32 "
                 "{%0,%1,%2,%3}, {%4,%5,%6,%7}, {%8,%9}, {%0,%1,%2,%3};"
                 : "+f"(c[0]), "+f"(c[1]), "+f"(c[2]), "+f"(c[3])
                 : "r"(a[0]), "r"(a[1]), "r"(a[2]), "r"(a[3]), "r"(b0), "r"(b1));
}

// ---------------- kernel 0: fold BN into conv weights ----------------------
__global__ void fold_kernel(Params P) {
    const int tid = threadIdx.x;
    {   const float *W = P.p[1], *g = P.p[2], *b = P.p[3], *m = P.p[4], *v = P.p[5];
        for (int i = tid; i < OUT_ * C_; i += 256) {
            int o = i >> 6;
            g_Wres[i] = W[i] * (g[o] / sqrtf(v[o] + EPSV));
        }
        for (int o = tid; o < OUT_; o += 256) {
            float s = g[o] / sqrtf(v[o] + EPSV);
            g_bres[o] = b[o] - m[o] * s;
        }
    }
    {   const float *W = P.p[6], *g = P.p[7], *b = P.p[8], *m = P.p[9], *v = P.p[10];
        for (int i = tid; i < HB_ * C_; i += 256) {
            int o = i >> 6;
            g_Wbot[i] = W[i] * (g[o] / sqrtf(v[o] + EPSV));
        }
        for (int o = tid; o < HB_; o += 256) {
            float s = g[o] / sqrtf(v[o] + EPSV);
            g_bbot[o] = b[o] - m[o] * s;
        }
    }
    {   const float *W = P.p[11], *g = P.p[12], *b = P.p[13], *m = P.p[14], *v = P.p[15];
        for (int i = tid; i < 32 * 32; i += 256) {
            int o = i >> 5;
            g_Wg1[i] = W[i] * (g[o] / sqrtf(v[o] + EPSV));
        }
        for (int o = tid; o < 32; o += 256) {
            float s = g[o] / sqrtf(v[o] + EPSV);
            g_bg1[o] = b[o] - m[o] * s;
        }
    }
    {   const float *W = P.p[16], *g = P.p[17], *b = P.p[18], *m = P.p[19], *v = P.p[20];
        for (int i = tid; i < 32 * 32; i += 256) {
            int o = i >> 5;
            g_Wg2[i] = W[i] * (g[o] / sqrtf(v[o] + EPSV));
        }
        for (int o = tid; o < 32; o += 256) {
            float s = g[o] / sqrtf(v[o] + EPSV);
            g_bg2[o] = b[o] - m[o] * s;
        }
    }
    {   const float *W = P.p[21], *g = P.p[22], *b = P.p[23], *m = P.p[24], *v = P.p[25];
        for (int i = tid; i < OUT_ * 96; i += 256) {
            int o = i / 96;
            g_Wdec[i] = W[i] * (g[o] / sqrtf(v[o] + EPSV));
        }
        for (int o = tid; o < OUT_; o += 256) {
            float s = g[o] / sqrtf(v[o] + EPSV);
            g_bdec[o] = b[o] - m[o] * s;
        }
    }
}

// ---------------- kernel 1: transpose x -> bf16 hi/lo split + sq -----------
__global__ __launch_bounds__(256) void prep_kernel(const float* __restrict__ x) {
    __shared__ float t[64][65];
    const int b = blockIdx.y, n0 = blockIdx.x * 64;
    for (int i = threadIdx.x; i < 64 * 64; i += 256) {
        int c = i >> 6, nn = i & 63;
        t[c][nn] = x[(b * C_ + c) * N_ + n0 + nn];
    }
    __syncthreads();
    for (int i = threadIdx.x; i < 64 * 64; i += 256) {
        int nn = i >> 6, c = i & 63;
        float val = t[c][nn];
        __nv_bfloat16 h = __float2bfloat16(val);
        float lo = val - __bfloat162float(h);
        size_t base = ((size_t)(b * N_ + n0 + nn)) * 128;
        g_pbf[base + c]      = h;
        g_pbf[base + 64 + c] = __float2bfloat16(lo);
    }
    if (threadIdx.x < 64) {
        float s = 0.f;
#pragma unroll
        for (int c = 0; c < 64; c++) { float v = t[c][threadIdx.x]; s += v * v; }
        g_sq[b * N_ + n0 + threadIdx.x] = s;
    }
}

// ---------------- kernel 2: res branch (-> d_out) + bottleneck (-> g_hb) ---
// 256 threads: 64 points x 4 output-groups (each thread: 32 res + 4 bot)
__global__ __launch_bounds__(256) void conv1_kernel(const float* __restrict__ x,
                                                    float* __restrict__ out) {
    __shared__ float WresS[OUT_ * C_];   // 32 KB
    __shared__ float WbotS[HB_ * C_];
    __shared__ float bresS[OUT_], bbotS[HB_];
    const int tid = threadIdx.x;
    const int b = blockIdx.y;
    const int p = tid & 63;
    const int h = tid >> 6;              // 0..3
    const int n = blockIdx.x * 64 + p;
    for (int i = tid; i < OUT_ * C_; i += 256) WresS[i] = g_Wres[i];
    for (int i = tid; i < HB_ * C_; i += 256)  WbotS[i] = g_Wbot[i];
    if (tid < OUT_) bresS[tid] = g_bres[tid];
    if (tid < HB_)  bbotS[tid] = g_bbot[tid];
    __syncthreads();

    float xv[64];
#pragma unroll
    for (int c = 0; c < 64; c++) xv[c] = x[(b * C_ + c) * N_ + n];

    const int oR = h * 32;
#pragma unroll 4
    for (int oo = 0; oo < 32; oo++) {
        const int o = oR + oo;
        const float4* w4 = (const float4*)(WresS + o * 64);
        float s0 = 0.f, s1 = 0.f, s2 = 0.f, s3 = 0.f;
#pragma unroll
        for (int i = 0; i < 16; i++) {
            float4 wv = w4[i];
            s0 += wv.x * xv[4 * i + 0];
            s1 += wv.y * xv[4 * i + 1];
            s2 += wv.z * xv[4 * i + 2];
            s3 += wv.w * xv[4 * i + 3];
        }
        float acc = bresS[o] + ((s0 + s1) + (s2 + s3));
        out[(b * OUT_ + o) * N_ + n] = fmaxf(acc, 0.f);
    }
    const int oB = h * 4;
#pragma unroll
    for (int oo = 0; oo < 4; oo++) {
        const int o = oB + oo;
        const float4* w4 = (const float4*)(WbotS + o * 64);
        float s0 = 0.f, s1 = 0.f, s2 = 0.f, s3 = 0.f;
#pragma unroll
        for (int i = 0; i < 16; i++) {
            float4 wv = w4[i];
            s0 += wv.x * xv[4 * i + 0];
            s1 += wv.y * xv[4 * i + 1];
            s2 += wv.z * xv[4 * i + 2];
            s3 += wv.w * xv[4 * i + 3];
        }
        float acc = bbotS[o] + ((s0 + s1) + (s2 + s3));
        g_hb[(b * N_ + n) * HB_ + o] = fmaxf(acc, 0.f);
    }
}

// ---------------- kernel 3: FUSED d2 gemm + top-20 selection ---------------
// Block owns 64 rows; loops over 32 column tiles of 128. Per tile:
//   load Bs -> mma (identical arithmetic to previous gemm) -> d2 to smem ->
//   warp-collective select (identical candidate order & insert logic).
// No d2 matrix in DRAM. Output g_idx bitwise identical to previous rounds.
constexpr int SST = 136;          // bf16 row stride (272B, conflict-free ldsm)
constexpr int RT  = 64;           // rows per block
constexpr int D2ST = 136;         // d2 smem row stride in floats
constexpr int AS_BYTES = RT * SST * 2;          // 17408
constexpr int BS_BYTES = 128 * SST * 2;         // 34816
constexpr int D2_BYTES = RT * D2ST * 4;         // 34816
constexpr int FUSED_SMEM = AS_BYTES + BS_BYTES + D2_BYTES;   // 87040

__global__ __launch_bounds__(256) void d2knn_kernel() {
    extern __shared__ char dyn[];
    __nv_bfloat16* AsS = (__nv_bfloat16*)dyn;
    __nv_bfloat16* BsS = (__nv_bfloat16*)(dyn + AS_BYTES);
    float*         d2S = (float*)(dyn + AS_BYTES + BS_BYTES);

    const int tid = threadIdx.x;
    const int lane = tid & 31, warp = tid >> 5;
    const int b = blockIdx.y;
    const int m0 = blockIdx.x * RT;
    const int mBase = (warp >> 2) * 32;
    const int nBase = (warp & 3) * 32;
    const float* sqB = g_sq + b * N_;

    {   // load A tile (64 rows) once
        const uint4* srcA = (const uint4*)(g_pbf + ((size_t)(b * N_ + m0)) * 128);
        for (int i = tid; i < RT * 16; i += 256) {
            int r = i >> 4, c = i & 15;
            *(uint4*)((char*)AsS + r * 272 + c * 16) = srcA[i];
        }
    }

    // per-warp select state: 8 rows per warp, one list slot per lane per row
    float sd[8]; int si[8]; float thr[8];
#pragma unroll
    for (int rr = 0; rr < 8; rr++) { sd[rr] = 3.4e38f; si[rr] = 0x7fffffff; thr[rr] = 3.4e38f; }

    unsigned aBase = (unsigned)__cvta_generic_to_shared(AsS)
                   + ((mBase + (lane & 15)) * SST + ((lane >> 4) << 3)) * 2;
    unsigned bBase = (unsigned)__cvta_generic_to_shared(BsS)
                   + ((nBase + (lane & 7) + ((lane >> 4) << 3)) * SST + (((lane >> 3) & 1) << 3)) * 2;

    for (int j = 0; j < N_ / 128; j++) {
        __syncthreads();   // prev select done: Bs & d2S reusable (also covers A load, iter 0)
        {
            const uint4* srcB = (const uint4*)(g_pbf + ((size_t)(b * N_ + j * 128)) * 128);
            for (int i = tid; i < 2048; i += 256) {
                int r = i >> 4, c = i & 15;
                *(uint4*)((char*)BsS + r * 272 + c * 16) = srcB[i];
            }
        }
        __syncthreads();

        float acc[8][4];
#pragma unroll
        for (int t = 0; t < 8; t++) { acc[t][0] = acc[t][1] = acc[t][2] = acc[t][3] = 0.f; }

#pragma unroll
        for (int ks = 0; ks < 8; ks++) {
            unsigned a[2][4], bfr[2][4], bxr[2][4];
#pragma unroll
            for (int ii = 0; ii < 2; ii++)
                ldsm4(a[ii][0], a[ii][1], a[ii][2], a[ii][3],
                      aBase + ii * (16 * SST * 2) + ks * 32);
#pragma unroll
            for (int ii = 0; ii < 2; ii++)
                ldsm4(bfr[ii][0], bfr[ii][1], bfr[ii][2], bfr[ii][3],
                      bBase + ii * (16 * SST * 2) + ks * 32);
#pragma unroll
            for (int ii = 0; ii < 2; ii++)
                ldsm4(bxr[ii][0], bxr[ii][1], bxr[ii][2], bxr[ii][3],
                      bBase + ii * (16 * SST * 2) + (ks ^ 4) * 32);
#pragma unroll
            for (int ii = 0; ii < 2; ii++)
#pragma unroll
                for (int jj = 0; jj < 4; jj++) {
                    mma16816(acc[ii * 4 + jj], a[ii],
                             bfr[jj >> 1][(jj & 1) << 1], bfr[jj >> 1][((jj & 1) << 1) | 1]);
                    mma16816(acc[ii * 4 + jj], a[ii],
                             bxr[jj >> 1][(jj & 1) << 1], bxr[jj >> 1][((jj & 1) << 1) | 1]);
                }
        }

        // epilogue: d2 -> smem (same arithmetic as before)
        const int n0 = j * 128;
#pragma unroll
        for (int ii = 0; ii < 2; ii++) {
            int lr0 = mBase + ii * 16 + (lane >> 2);
            float smA = sqB[m0 + lr0], smB2 = sqB[m0 + lr0 + 8];
#pragma unroll
            for (int jj = 0; jj < 4; jj++) {
                int lc = nBase + jj * 8 + ((lane & 3) << 1);
                float snA = sqB[n0 + lc], snB = sqB[n0 + lc + 1];
                const float* t0 = acc[ii * 4 + jj];
                *(float2*)(d2S + lr0 * D2ST + lc) =
                    make_float2(fmaf(-2.f, t0[0], smA + snA), fmaf(-2.f, t0[1], smA + snB));
                *(float2*)(d2S + (lr0 + 8) * D2ST + lc) =
                    make_float2(fmaf(-2.f, t0[2], smB2 + snA), fmaf(-2.f, t0[3], smB2 + snB));
            }
        }
        __syncthreads();

        // select phase: warp handles rows warp*8 .. warp*8+7
#pragma unroll
        for (int rr = 0; rr < 8; rr++) {
            const int r = warp * 8 + rr;
            float4 v = *(const float4*)(d2S + r * D2ST + lane * 4);
            float m4 = fminf(fminf(v.x, v.y), fminf(v.z, v.w));
            if (!__ballot_sync(0xffffffffu, m4 <= thr[rr])) continue;
            const int base = n0 + lane * 4;
#pragma unroll
            for (int c = 0; c < 4; c++) {
                float d = (c == 0) ? v.x : (c == 1) ? v.y : (c == 2) ? v.z : v.w;
                int idx = base + c;
                unsigned ball = __ballot_sync(0xffffffffu, d <= thr[rr]);
                while (ball) {
                    int src = __ffs(ball) - 1;
                    float nd = __shfl_sync(0xffffffffu, d, src);
                    int   ni = __shfl_sync(0xffffffffu, idx, src);
                    bool pred = (sd[rr] > nd) || (sd[rr] == nd && si[rr] > ni);
                    unsigned pb = __ballot_sync(0xffffffffu, pred);
                    if (pb) {
                        int p = __ffs(pb) - 1;
                        float shd = __shfl_up_sync(0xffffffffu, sd[rr], 1);
                        int   shi = __shfl_up_sync(0xffffffffu, si[rr], 1);
                        if (lane > p)  { sd[rr] = shd; si[rr] = shi; }
                        if (lane == p) { sd[rr] = nd;  si[rr] = ni;  }
                        thr[rr] = __shfl_sync(0xffffffffu, sd[rr], 19);
                    }
                    ball &= ~(1u << src);
                    ball &= __ballot_sync(0xffffffffu, d <= thr[rr]);
                }
            }
        }
    }

#pragma unroll
    for (int rr = 0; rr < 8; rr++) {
        if (lane < K_)
            g_idx[((size_t)(b * N_ + m0 + warp * 8 + rr)) * K_ + lane] = si[rr];
    }
}

// ---------------- kernel 4: fused GCN (gather, g1, g2, gmax, decode) -------
__device__ __forceinline__ float dot16(const float* wv,
                                       float4 v0, float4 v1, float4 v2, float4 v3) {
    return wv[0] * v0.x + wv[1] * v0.y + wv[2]  * v0.z + wv[3]  * v0.w
         + wv[4] * v1.x + wv[5] * v1.y + wv[6]  * v1.z + wv[7]  * v1.w
         + wv[8] * v2.x + wv[9] * v2.y + wv[10] * v2.z + wv[11] * v2.w
         + wv[12]* v3.x + wv[13]* v3.y + wv[14] * v3.z + wv[15] * v3.w;
}

constexpr int WPB = 8;       // warps (points) per block
constexpr int WD_PAD = 100;  // padded row stride for Wdec (conflict-free float4)

__global__ __launch_bounds__(256) void gcn_kernel(float* __restrict__ out) {
    extern __shared__ float WdP[];              // [128][100] padded decode weights
    __shared__ float nbS[WPB][K_][HB_];
    __shared__ float ctrS[WPB][HB_];
    __shared__ float allfS[WPB][96];
    __shared__ int   idxS[WPB][K_];

    const int tid = threadIdx.x;
    const int w = tid >> 5, lane = tid & 31;
    const int b = blockIdx.y;
    const int n = blockIdx.x * WPB + w;

    for (int i = tid; i < OUT_ * 96; i += 256) {
        int o = i / 96, c = i - o * 96;
        WdP[o * WD_PAD + c] = g_Wdec[i];
    }

    float w1[32], w2[32];
    {
        const float4* w1p = (const float4*)(g_Wg1 + lane * 32);
        const float4* w2p = (const float4*)(g_Wg2 + lane * 32);
#pragma unroll
        for (int c4 = 0; c4 < 8; c4++) {
            float4 t1 = w1p[c4];
            w1[c4 * 4 + 0] = t1.x; w1[c4 * 4 + 1] = t1.y;
            w1[c4 * 4 + 2] = t1.z; w1[c4 * 4 + 3] = t1.w;
            float4 t2 = w2p[c4];
            w2[c4 * 4 + 0] = t2.x; w2[c4 * 4 + 1] = t2.y;
            w2[c4 * 4 + 2] = t2.z; w2[c4 * 4 + 3] = t2.w;
        }
    }
    const float b1 = g_bg1[lane], b2 = g_bg2[lane];

    if (lane < K_)  idxS[w][lane] = g_idx[(b * N_ + n) * K_ + lane];
    if (lane < HB_) ctrS[w][lane] = g_hb[(b * N_ + n) * HB_ + lane];
    __syncwarp();

    for (int t = lane; t < K_ * HB_; t += 32) {
        int k = t >> 4, c = t & 15;
        nbS[w][k][c] = g_hb[(b * N_ + idxS[w][k]) * HB_ + c];
    }
    __syncthreads();   // also covers WdP load

    float pre1 = b1, pre2 = b2;
#pragma unroll
    for (int c = 0; c < 16; c++) {
        float cv = ctrS[w][c];
        pre1 += w1[16 + c] * cv;
        pre2 += w2[16 + c] * cv;
    }

    float acc1 = -3.4e38f, acc2 = -3.4e38f;
#pragma unroll
    for (int k = 0; k < K_; k++) {
        const float4* nb4 = (const float4*)nbS[w][k];
        float4 v0 = nb4[0], v1 = nb4[1], v2 = nb4[2], v3 = nb4[3];
        float y = pre1 + dot16(w1, v0, v1, v2, v3);
        float ly = y > 0.f ? y : 0.2f * y;
        acc1 = fmaxf(acc1, ly);
        if ((k & 1) == 0) {
            float y2 = pre2 + dot16(w2, v0, v1, v2, v3);
            float ly2 = y2 > 0.f ? y2 : 0.2f * y2;
            acc2 = fmaxf(acc2, ly2);
        }
    }

    float gm = -3.4e38f;
    if (lane < 16) {
#pragma unroll
        for (int k = 0; k < K_; k++) gm = fmaxf(gm, nbS[w][k][lane]);
    }
    allfS[w][lane]      = acc1;
    allfS[w][32 + lane] = acc2;
    allfS[w][64 + lane] = (lane < 16) ? gm : ctrS[w][lane - 16];
    __syncwarp();

    float accd0 = g_bdec[lane],      accd1 = g_bdec[lane + 32];
    float accd2 = g_bdec[lane + 64], accd3 = g_bdec[lane + 96];
    const float4* af4 = (const float4*)allfS[w];
    const float4* wr0 = (const float4*)(WdP + (lane)      * WD_PAD);
    const float4* wr1 = (const float4*)(WdP + (lane + 32) * WD_PAD);
    const float4* wr2 = (const float4*)(WdP + (lane + 64) * WD_PAD);
    const float4* wr3 = (const float4*)(WdP + (lane + 96) * WD_PAD);
#pragma unroll
    for (int c4 = 0; c4 < 24; c4++) {
        float4 a = af4[c4];
        float4 q0 = wr0[c4]; accd0 += q0.x*a.x + q0.y*a.y + q0.z*a.z + q0.w*a.w;
        float4 q1 = wr1[c4]; accd1 += q1.x*a.x + q1.y*a.y + q1.z*a.z + q1.w*a.w;
        float4 q2 = wr2[c4]; accd2 += q2.x*a.x + q2.y*a.y + q2.z*a.z + q2.w*a.w;
        float4 q3 = wr3[c4]; accd3 += q3.x*a.x + q3.y*a.y + q3.z*a.z + q3.w*a.w;
    }
    {
        int i0 = (b * OUT_ + lane)      * N_ + n;
        int i1 = (b * OUT_ + lane + 32) * N_ + n;
        int i2 = (b * OUT_ + lane + 64) * N_ + n;
        int i3 = (b * OUT_ + lane + 96) * N_ + n;
        float r0 = out[i0], r1 = out[i1], r2 = out[i2], r3 = out[i3];
        out[i0] = fmaxf(accd0, 0.f) + r0;
        out[i1] = fmaxf(accd1, 0.f) + r1;
        out[i2] = fmaxf(accd2, 0.f) + r2;
        out[i3] = fmaxf(accd3, 0.f) + r3;
    }
}

// ---------------- launch ---------------------------------------------------
extern "C" void kernel_launch(void* const* d_in, const int* in_sizes, int n_in,
                              void* d_out, int out_size) {
    Params P;
    for (int i = 0; i < 26; i++) P.p[i] = (const float*)d_in[i];
    const float* x = P.p[0];
    float* out = (float*)d_out;

    cudaFuncSetAttribute(d2knn_kernel, cudaFuncAttributeMaxDynamicSharedMemorySize, FUSED_SMEM);
    cudaFuncSetAttribute(gcn_kernel, cudaFuncAttributeMaxDynamicSharedMemorySize,
                         OUT_ * WD_PAD * (int)sizeof(float));

    fold_kernel<<<1, 256>>>(P);
    prep_kernel<<<dim3(N_ / 64, B_), 256>>>(x);
    conv1_kernel<<<dim3(N_ / 64, B_), 256>>>(x, out);
    d2knn_kernel<<<dim3(N_ / RT, B_), 256, FUSED_SMEM>>>();
    gcn_kernel<<<dim3(N_ / WPB, B_), 256, OUT_ * WD_PAD * (int)sizeof(float)>>>(out);
}